// round 3
// baseline (speedup 1.0000x reference)
#include <cuda_runtime.h>
#include <math.h>

// Problem constants
#define NB    4096
#define DD    20
#define HH    256
#define WW    256
#define HD    5120
#define NSEG  63
#define NSTEPS 126

// ---------------- device scratch (static globals: allocation-guard safe) ----
__device__ float g_z  [NB * HH];
__device__ float g_h2 [NB * WW];
__device__ float g_kA [4][NB * HH];   // split-K half A of k1..k4
__device__ float g_kB [4][NB * HH];   // split-K half B
__device__ float g_W3t[HD * HH];      // W3 transposed: [w*20+d][h]
__device__ unsigned g_barrier;

// ---------------------------------------------------------------- barrier
__global__ void reset_barrier() { g_barrier = 0u; }

__device__ __forceinline__ void grid_bar(int G, unsigned& target) {
    __syncthreads();
    if (threadIdx.x == 0) {
        __threadfence();                       // drain my writes to L2
        atomicAdd(&g_barrier, 1u);
        target += (unsigned)G;
        while (*((volatile unsigned*)&g_barrier) < target) { __nanosleep(32); }
        __threadfence();                       // invalidate stale L1
    }
    __syncthreads();
}

// ---------------------------------------------------------------- transpose
__global__ void transpose_w3(const float* __restrict__ W3) {
    int o = blockIdx.x * 256 + threadIdx.x;      // o < 5120*256
    int h  = o & 255;
    int kk = o >> 8;                              // w*20+d
    int w  = kk / 20;
    int d  = kk - w * 20;
    g_W3t[o] = W3[w * HD + h * DD + d];
}

// ------------------------------------------------------------------ z0 init
__global__ void init_z(const float* __restrict__ coeffs,
                       const float* __restrict__ Wi,
                       const float* __restrict__ bi) {
    int b = blockIdx.x;
    int c = threadIdx.x;
    __shared__ float a[DD];
    if (c < DD) a[c] = coeffs[(size_t)b * NSEG * 80 + c];
    __syncthreads();
    float s = bi[c];
#pragma unroll
    for (int d = 0; d < DD; d++) s += a[d] * Wi[d * HH + c];
    g_z[b * HH + c] = s;
}

// ======================= persistent time-loop kernel ========================
__global__ void __launch_bounds__(256, 2)
persist(const float* __restrict__ coeffs,
        const float* __restrict__ W1, const float* __restrict__ b1,
        const float* __restrict__ W2, const float* __restrict__ b2,
        const float* __restrict__ b3, int G)
{
    __shared__ float As[40][128];     // 20 KB
    __shared__ float Bs[40][64];      // 10 KB
    __shared__ float dXs[128][20];    // 10 KB
    float (*S)[20] = (float(*)[20])&As[0][0];   // MLP overlay: 256x20 = 20 KB

    const int tid = threadIdx.x;
    unsigned target = 0;

#pragma unroll 1
    for (int step = 0; step < NSTEPS; step++) {
        float tbase = (float)step * 0.5f;
#pragma unroll 1
        for (int s = 0; s < 4; s++) {
            const float off = (s == 0) ? 0.0f : ((s == 3) ? 0.5f : 0.25f);
            float ts = tbase + off;
            int iseg = (int)ts;
            if (iseg > NSEG - 1) iseg = NSEG - 1;
            float u  = ts - (float)iseg;

            // ------------------------------ MLP phase ------------------------------
#pragma unroll 1
            for (int j = blockIdx.x; j < 256; j += G) {
                int row0 = j * 16;
#pragma unroll
                for (int r = 0; r < 16; r++) {
                    int idx = (row0 + r) * HH + tid;
                    float v = g_z[idx];
                    if (s == 0) {
                        if (step > 0) {
                            float k1 = g_kA[0][idx] + g_kB[0][idx];
                            float k2 = g_kA[1][idx] + g_kB[1][idx];
                            float k3 = g_kA[2][idx] + g_kB[2][idx];
                            float k4 = g_kA[3][idx] + g_kB[3][idx];
                            v += (1.f / 12.f) * (k1 + 2.f * k2 + 2.f * k3 + k4);
                            g_z[idx] = v;
                        }
                    } else {
                        v += off * (g_kA[s - 1][idx] + g_kB[s - 1][idx]);
                    }
                    S[tid][r] = v;
                }
                __syncthreads();

                // layer 1: chunked accumulation (4 chunks of 64 i's)
                float accM[16], accL[16];
#pragma unroll
                for (int r = 0; r < 16; r++) accM[r] = 0.f;
#pragma unroll 1
                for (int ch = 0; ch < 4; ch++) {
#pragma unroll
                    for (int r = 0; r < 16; r++) accL[r] = 0.f;
#pragma unroll 4
                    for (int ii = 0; ii < 64; ii++) {
                        int i = ch * 64 + ii;
                        float w = W1[i * 256 + tid];
#pragma unroll
                        for (int r4 = 0; r4 < 4; r4++) {
                            float4 zv = *(const float4*)&S[i][r4 * 4];
                            accL[r4*4+0] += zv.x * w;  accL[r4*4+1] += zv.y * w;
                            accL[r4*4+2] += zv.z * w;  accL[r4*4+3] += zv.w * w;
                        }
                    }
#pragma unroll
                    for (int r = 0; r < 16; r++) accM[r] += accL[r];
                }
                float bb = b1[tid];
                __syncthreads();
#pragma unroll
                for (int r = 0; r < 16; r++) S[tid][r] = tanhf(accM[r] + bb);
                __syncthreads();

                // layer 2
#pragma unroll
                for (int r = 0; r < 16; r++) accM[r] = 0.f;
#pragma unroll 1
                for (int ch = 0; ch < 4; ch++) {
#pragma unroll
                    for (int r = 0; r < 16; r++) accL[r] = 0.f;
#pragma unroll 4
                    for (int ii = 0; ii < 64; ii++) {
                        int i = ch * 64 + ii;
                        float w = W2[i * 256 + tid];
#pragma unroll
                        for (int r4 = 0; r4 < 4; r4++) {
                            float4 zv = *(const float4*)&S[i][r4 * 4];
                            accL[r4*4+0] += zv.x * w;  accL[r4*4+1] += zv.y * w;
                            accL[r4*4+2] += zv.z * w;  accL[r4*4+3] += zv.w * w;
                        }
                    }
#pragma unroll
                    for (int r = 0; r < 16; r++) accM[r] += accL[r];
                }
                bb = b2[tid];
#pragma unroll
                for (int r = 0; r < 16; r++)
                    g_h2[(row0 + r) * WW + tid] = tanhf(accM[r] + bb);
                __syncthreads();              // protect S before next job
            }
            grid_bar(G, target);

            // ------------------------------ GEMM phase ------------------------------
            // C[b,h] = sum_{w,d} h2[b,w]*dX[b,d]*W3t[w*20+d,h]  (+ b3 term, split 0)
#pragma unroll 1
            for (int j = blockIdx.x; j < 256; j += G) {
                const int mt = j >> 3;            // 0..31
                const int nt = (j >> 1) & 3;      // 0..3
                const int bz = j & 1;             // split-K half
                const int row0  = mt * 128;
                const int col0  = nt * 64;
                const int wbase = bz * 128;

                {   // dX for this tile's 128 rows
                    float u2 = 2.f * u, u3 = 3.f * u * u;
                    for (int idx = tid; idx < 128 * 20; idx += 256) {
                        int r = idx / 20, d = idx - r * 20;
                        const float* cp = coeffs + ((size_t)(row0 + r) * NSEG + iseg) * 80;
                        dXs[r][d] = cp[20 + d] + u2 * cp[40 + d] + u3 * cp[60 + d];
                    }
                }
                __syncthreads();

                const int ty = tid >> 4;   // row group (8 rows)
                const int tx = tid & 15;   // col group (4 cols)
                const int am = tid >> 1;   // A-build row
                const int aw = tid & 1;    // A-build w within tile

                float accM[8][4];
#pragma unroll
                for (int i = 0; i < 8; i++)
#pragma unroll
                    for (int jj = 0; jj < 4; jj++) accM[i][jj] = 0.f;

                const float* Bg_base = g_W3t + ((size_t)bz * 2560) * 256 + col0;

#pragma unroll 1
                for (int kt = 0; kt < 64; kt++) {
                    const float* Bg = Bg_base + (size_t)kt * 40 * 256;
                    for (int idx = tid; idx < 40 * 64; idx += 256) {
                        int kk = idx >> 6, cc = idx & 63;
                        Bs[kk][cc] = Bg[kk * 256 + cc];
                    }
                    {
                        int w0 = wbase + kt * 2;
                        float hv = g_h2[(row0 + am) * WW + w0 + aw];
#pragma unroll
                        for (int d = 0; d < 20; d++)
                            As[aw * 20 + d][am] = hv * dXs[am][d];
                    }
                    __syncthreads();

                    // local chunk accumulator: 40 terms, then fold into main
                    float accL[8][4];
#pragma unroll
                    for (int i = 0; i < 8; i++)
#pragma unroll
                        for (int jj = 0; jj < 4; jj++) accL[i][jj] = 0.f;

#pragma unroll
                    for (int k = 0; k < 40; k++) {
                        float a[8], b[4];
                        *(float4*)&a[0] = *(const float4*)&As[k][ty * 8];
                        *(float4*)&a[4] = *(const float4*)&As[k][ty * 8 + 4];
                        *(float4*)&b[0] = *(const float4*)&Bs[k][tx * 4];
#pragma unroll
                        for (int i = 0; i < 8; i++)
#pragma unroll
                            for (int jj = 0; jj < 4; jj++)
                                accL[i][jj] += a[i] * b[jj];
                    }
#pragma unroll
                    for (int i = 0; i < 8; i++)
#pragma unroll
                        for (int jj = 0; jj < 4; jj++) accM[i][jj] += accL[i][jj];
                    __syncthreads();
                }

                float* kdst = (bz == 0) ? g_kA[s] : g_kB[s];
#pragma unroll
                for (int i = 0; i < 8; i++) {
                    int r = row0 + ty * 8 + i;
                    if (bz == 0) {
#pragma unroll
                        for (int jj = 0; jj < 4; jj++) {
                            int h = col0 + tx * 4 + jj;
                            const float* bp = b3 + h * 20;
                            float sb = 0.f;
#pragma unroll
                            for (int d = 0; d < 20; d++) sb += bp[d] * dXs[ty * 8 + i][d];
                            accM[i][jj] += sb;
                        }
                    }
                    *(float4*)&kdst[(size_t)r * 256 + col0 + tx * 4] = *(float4*)&accM[i][0];
                }
                __syncthreads();              // protect dXs before next job
            }
            grid_bar(G, target);
        }
    }
}

// --------------------------------------------------------------- final head
__device__ __forceinline__ float blockSum(float v, volatile float* s8) {
#pragma unroll
    for (int o = 16; o > 0; o >>= 1) v += __shfl_down_sync(0xffffffffu, v, o);
    if ((threadIdx.x & 31) == 0) s8[threadIdx.x >> 5] = v;
    __syncthreads();
    float t = 0.f;
#pragma unroll
    for (int i = 0; i < 8; i++) t += s8[i];
    __syncthreads();
    return t;
}

__global__ void head_kernel(const float* __restrict__ Ws,  const float* __restrict__ bs,
                            const float* __restrict__ lng, const float* __restrict__ lnb,
                            const float* __restrict__ Winf, const float* __restrict__ binf,
                            const float* __restrict__ Wdet, const float* __restrict__ bdet,
                            const float* __restrict__ Wsur, const float* __restrict__ bsur,
                            float* __restrict__ out) {
    int b = blockIdx.x;
    int c = threadIdx.x;
    __shared__ float zs[256];
    __shared__ float s8[8];

    {   // final RK4 update of z (last step's k's never folded back)
        int idx = b * HH + c;
        float k1 = g_kA[0][idx] + g_kB[0][idx];
        float k2 = g_kA[1][idx] + g_kB[1][idx];
        float k3 = g_kA[2][idx] + g_kB[2][idx];
        float k4 = g_kA[3][idx] + g_kB[3][idx];
        zs[c] = g_z[idx] + (1.f / 12.f) * (k1 + 2.f * k2 + 2.f * k3 + k4);
    }
    __syncthreads();

    // h = z@Ws + bs with 4-way chunked accumulation
    float h = 0.f;
#pragma unroll 1
    for (int ch = 0; ch < 4; ch++) {
        float hl = 0.f;
#pragma unroll 4
        for (int ii = 0; ii < 64; ii++) {
            int i = ch * 64 + ii;
            hl += zs[i] * Ws[i * 256 + c];
        }
        h += hl;
    }
    h += bs[c];

    float mu  = blockSum(h, s8) * (1.f / 256.f);
    float dc  = h - mu;
    float var = blockSum(dc * dc, s8) * (1.f / 256.f);
    float r   = lng[c] * dc * rsqrtf(var + 1e-5f) + lnb[c];
    r = fmaxf(r, 0.f);

    out[36864 + (size_t)b * 256 + c] = r;   // r block after 4096*(4+3+2)

#pragma unroll
    for (int o = 0; o < 4; o++) {
        float s = blockSum(r * Winf[c * 4 + o], s8);
        if (c == 0) out[(size_t)b * 4 + o] = 1.f / (1.f + expf(-(s + binf[o])));
    }
#pragma unroll
    for (int o = 0; o < 3; o++) {
        float s = blockSum(r * Wdet[c * 3 + o], s8);
        if (c == 0) out[16384 + (size_t)b * 3 + o] = 1.f / (1.f + expf(-(s + bdet[o])));
    }
#pragma unroll
    for (int o = 0; o < 2; o++) {
        float s = blockSum(r * Wsur[c * 2 + o], s8);
        if (c == 0) {
            float x = s + bsur[o];
            out[28672 + (size_t)b * 2 + o] = fmaxf(x, 0.f) + log1pf(expf(-fabsf(x)));
        }
    }
}

// =========================================================== host dispatch
extern "C" void kernel_launch(void* const* d_in, const int* in_sizes, int n_in,
                              void* d_out, int out_size) {
    const float* coeffs = (const float*)d_in[0];
    const float* Wi     = (const float*)d_in[1];
    const float* bi     = (const float*)d_in[2];
    const float* W1     = (const float*)d_in[3];
    const float* b1     = (const float*)d_in[4];
    const float* W2     = (const float*)d_in[5];
    const float* b2     = (const float*)d_in[6];
    const float* W3     = (const float*)d_in[7];
    const float* b3     = (const float*)d_in[8];
    const float* Ws     = (const float*)d_in[9];
    const float* bs     = (const float*)d_in[10];
    const float* lng    = (const float*)d_in[11];
    const float* lnb    = (const float*)d_in[12];
    const float* Winf   = (const float*)d_in[13];
    const float* binf   = (const float*)d_in[14];
    const float* Wdet   = (const float*)d_in[15];
    const float* bdet   = (const float*)d_in[16];
    const float* Wsur   = (const float*)d_in[17];
    const float* bsur   = (const float*)d_in[18];
    float* out = (float*)d_out;

    int dev = 0, sm = 148, occ = 0;
    cudaGetDevice(&dev);
    cudaDeviceGetAttribute(&sm, cudaDevAttrMultiProcessorCount, dev);
    cudaOccupancyMaxActiveBlocksPerMultiprocessor(&occ, persist, 256, 0);
    if (occ < 1) occ = 1;
    int G = sm * occ;
    if (G > 256) G = 256;

    reset_barrier<<<1, 1>>>();
    transpose_w3<<<HD * HH / 256, 256>>>(W3);
    init_z<<<NB, 256>>>(coeffs, Wi, bi);
    persist<<<G, 256>>>(coeffs, W1, b1, W2, b2, b3, G);
    head_kernel<<<NB, 256>>>(Ws, bs, lng, lnb, Winf, binf, Wdet, bdet, Wsur, bsur, out);
}

// round 10
// speedup vs baseline: 1.4574x; 1.4574x over previous
#include <cuda_runtime.h>
#include <cuda_bf16.h>
#include <stdint.h>
#include <cstdint>
#include <math.h>

// Problem constants
#define NB    4096
#define DD    20
#define HH    256
#define HD    5120
#define NSEG  63
#define NSTEPS 126
#define GRID  128          // 64 M-tiles(64 rows) x 2 N-tiles(2560 hd-cols)

// ---------------- device scratch ----------------
__device__ float g_z [NB * HH];
__device__ float g_k [4][NB * HH];              // k1..k4
__device__ __nv_bfloat16 g_h2s0[NB * HH];       // h2 3-way bf16 split (A operand)
__device__ __nv_bfloat16 g_h2s1[NB * HH];
__device__ __nv_bfloat16 g_h2s2[NB * HH];
__device__ __nv_bfloat16 g_B0[HD * HH];         // W3^T 3-way bf16 split: [hd][w]
__device__ __nv_bfloat16 g_B1[HD * HH];
__device__ __nv_bfloat16 g_B2[HD * HH];
__device__ unsigned g_barrier;

// ---------------- SMEM layout (bytes) ----------------
#define OFF_DX   0           // float[64][20]             = 5120
#define OFF_B3S  5120        // b3 slice [2560] fp32      = 10240 -> 15360
#define OFF_A0   15360       // A split0: 64 x 264 bf16   = 33792
#define OFF_A1   49152
#define OFF_A2   82944       // -> 116736
#define OFF_B0   116736      // B split0: 160 x 72 bf16   = 23040
#define OFF_B1   139776
#define OFF_B2   162816      // -> 185856
#define OFF_G    185856      // G tile [64][164] fp32     = 41984 -> 227840
#define SMEM_TOTAL 227840
#define APITCH 264           // bf16/row (256 + 8 pad)
#define BPITCH 72            // bf16/row (64 + 8 pad)
#define GPITCH 164

// ---------------- PTX helpers (baseline sm_80-class only) ----------------
__device__ __forceinline__ uint32_t s2u(const void* p) {
    uint32_t a;
    asm("{ .reg .u64 t; cvta.to.shared.u64 t, %1; cvt.u32.u64 %0, t; }" : "=r"(a) : "l"(p));
    return a;
}
#define LDSM4(r, addr) \
    asm volatile("ldmatrix.sync.aligned.m8n8.x4.shared.b16 {%0,%1,%2,%3}, [%4];" \
        : "=r"((r)[0]),"=r"((r)[1]),"=r"((r)[2]),"=r"((r)[3]) : "r"(addr))
#define LDSM2(r, addr) \
    asm volatile("ldmatrix.sync.aligned.m8n8.x2.shared.b16 {%0,%1}, [%2];" \
        : "=r"((r)[0]),"=r"((r)[1]) : "r"(addr))
// accumulate into d (d = A*B + d)
#define MMA16(c, a, b0, b1) \
    asm volatile("mma.sync.aligned.m16n8k16.row.col.f32.bf16.bf16.f32 " \
        "{%0,%1,%2,%3},{%4,%5,%6,%7},{%8,%9},{%0,%1,%2,%3};" \
        : "+f"((c)[0]),"+f"((c)[1]),"+f"((c)[2]),"+f"((c)[3]) \
        : "r"((a)[0]),"r"((a)[1]),"r"((a)[2]),"r"((a)[3]),"r"(b0),"r"(b1))
// init: d = A*B + 0   (zero c-operand, fresh chain)
#define MMA16_INIT(d, a, b0, b1, z) \
    asm volatile("mma.sync.aligned.m16n8k16.row.col.f32.bf16.bf16.f32 " \
        "{%0,%1,%2,%3},{%4,%5,%6,%7},{%8,%9},{%10,%11,%12,%13};" \
        : "=f"((d)[0]),"=f"((d)[1]),"=f"((d)[2]),"=f"((d)[3]) \
        : "r"((a)[0]),"r"((a)[1]),"r"((a)[2]),"r"((a)[3]),"r"(b0),"r"(b1), \
          "f"(z),"f"(z),"f"(z),"f"(z))

// ---------------- small kernels ----------------
__global__ void reset_barrier() { g_barrier = 0u; }

__device__ __forceinline__ void grid_bar(int G, unsigned& target) {
    __syncthreads();
    if (threadIdx.x == 0) {
        __threadfence();
        atomicAdd(&g_barrier, 1u);
        target += (unsigned)G;
        while (*((volatile unsigned*)&g_barrier) < target) { __nanosleep(32); }
        __threadfence();
    }
    __syncthreads();
}

// W3[w, hd] -> B0/B1/B2[hd, w] (3-way bf16 split, transposed)
__global__ void split_w3(const float* __restrict__ W3) {
    int o = blockIdx.x * 256 + threadIdx.x;   // < 5120*256
    int hd = o >> 8;
    int w  = o & 255;
    float v = W3[(size_t)w * HD + hd];
    __nv_bfloat16 p0 = __float2bfloat16(v);
    float r = v - __bfloat162float(p0);
    __nv_bfloat16 p1 = __float2bfloat16(r);
    r -= __bfloat162float(p1);
    __nv_bfloat16 p2 = __float2bfloat16(r);
    g_B0[o] = p0;  g_B1[o] = p1;  g_B2[o] = p2;
}

__global__ void init_z(const float* __restrict__ coeffs,
                       const float* __restrict__ Wi,
                       const float* __restrict__ bi) {
    int b = blockIdx.x;
    int c = threadIdx.x;
    __shared__ float a[DD];
    if (c < DD) a[c] = coeffs[(size_t)b * NSEG * 80 + c];
    __syncthreads();
    float s = bi[c];
#pragma unroll
    for (int d = 0; d < DD; d++) s += a[d] * Wi[d * HH + c];
    g_z[b * HH + c] = s;
}

// ======================= persistent time-loop kernel ========================
__global__ void __launch_bounds__(256)
persist(const float* __restrict__ coeffs,
        const float* __restrict__ W1, const float* __restrict__ b1,
        const float* __restrict__ W2, const float* __restrict__ b2,
        const float* __restrict__ b3, int G)
{
    extern __shared__ char smem[];
    const uint32_t sb = s2u(smem);
    const int tid  = threadIdx.x;
    const int wid  = tid >> 5;
    const int lane = tid & 31;

    float* dXs = (float*)(smem + OFF_DX);
    float* b3s = (float*)(smem + OFF_B3S);
    float* sG  = (float*)(smem + OFF_G);
    float* Sf  = (float*)(smem + OFF_A0);     // MLP overlay [256][36]

    unsigned target = 0;
    const int mt = blockIdx.x >> 1;           // M tile (0..63), 64 rows
    const int nt = blockIdx.x & 1;            // N tile (0..1), 2560 hd-cols
    const int row0g = mt * 64;
    const int col0  = nt * 2560;
    const int row0m = blockIdx.x * 32;        // MLP rows

    const int wm = wid >> 2, wn = wid & 3;    // warp grid 2(m) x 4(n), tile 32x40
    const uint32_t lma = (uint32_t)(lane & 15) * (APITCH * 2) + (uint32_t)((lane >> 4) & 1) * 16;
    const uint32_t lmb = (uint32_t)(lane & 7) * (BPITCH * 2) + (uint32_t)((lane >> 3) & 1) * 16;
    const float zc = 0.f;                     // zero c-operand

    // one-time: this block's b3 slice (stationary)
    for (int i = tid; i < 2560; i += 256) b3s[i] = b3[col0 + i];

#pragma unroll 1
    for (int step = 0; step < NSTEPS; step++) {
        float tbase = (float)step * 0.5f;
#pragma unroll 1
        for (int s = 0; s < 4; s++) {
            const float off = (s == 0) ? 0.0f : ((s == 3) ? 0.5f : 0.25f);
            float ts = tbase + off;
            int iseg = (int)ts;
            if (iseg > NSEG - 1) iseg = NSEG - 1;
            float u = ts - (float)iseg;

            // =========================== MLP (SIMT fp32) ===========================
            {
#pragma unroll
                for (int r = 0; r < 32; r++) {
                    int idx = (row0m + r) * HH + tid;
                    float v = g_z[idx];
                    if (s == 0) {
                        if (step > 0) {
                            float k1 = g_k[0][idx], k2 = g_k[1][idx];
                            float k3 = g_k[2][idx], k4 = g_k[3][idx];
                            v += (1.f / 12.f) * (k1 + 2.f * k2 + 2.f * k3 + k4);
                            g_z[idx] = v;
                        }
                    } else {
                        v += off * g_k[s - 1][idx];
                    }
                    Sf[tid * 36 + r] = v;
                }
                __syncthreads();

                float accM[32], accL[32];
#pragma unroll
                for (int r = 0; r < 32; r++) accM[r] = 0.f;
#pragma unroll 1
                for (int ch = 0; ch < 8; ch++) {
#pragma unroll
                    for (int r = 0; r < 32; r++) accL[r] = 0.f;
#pragma unroll 4
                    for (int ii = 0; ii < 32; ii++) {
                        int i = ch * 32 + ii;
                        float w = W1[i * 256 + tid];
#pragma unroll
                        for (int r4 = 0; r4 < 8; r4++) {
                            float4 zv = *(const float4*)&Sf[i * 36 + r4 * 4];
                            accL[r4*4+0] += zv.x * w;  accL[r4*4+1] += zv.y * w;
                            accL[r4*4+2] += zv.z * w;  accL[r4*4+3] += zv.w * w;
                        }
                    }
#pragma unroll
                    for (int r = 0; r < 32; r++) accM[r] += accL[r];
                }
                float bb = b1[tid];
                __syncthreads();
#pragma unroll
                for (int r = 0; r < 32; r++) Sf[tid * 36 + r] = tanhf(accM[r] + bb);
                __syncthreads();

#pragma unroll
                for (int r = 0; r < 32; r++) accM[r] = 0.f;
#pragma unroll 1
                for (int ch = 0; ch < 8; ch++) {
#pragma unroll
                    for (int r = 0; r < 32; r++) accL[r] = 0.f;
#pragma unroll 4
                    for (int ii = 0; ii < 32; ii++) {
                        int i = ch * 32 + ii;
                        float w = W2[i * 256 + tid];
#pragma unroll
                        for (int r4 = 0; r4 < 8; r4++) {
                            float4 zv = *(const float4*)&Sf[i * 36 + r4 * 4];
                            accL[r4*4+0] += zv.x * w;  accL[r4*4+1] += zv.y * w;
                            accL[r4*4+2] += zv.z * w;  accL[r4*4+3] += zv.w * w;
                        }
                    }
#pragma unroll
                    for (int r = 0; r < 32; r++) accM[r] += accL[r];
                }
                bb = b2[tid];
#pragma unroll
                for (int r = 0; r < 32; r++) {
                    float v = tanhf(accM[r] + bb);
                    __nv_bfloat16 p0 = __float2bfloat16(v);
                    float rr = v - __bfloat162float(p0);
                    __nv_bfloat16 p1 = __float2bfloat16(rr);
                    rr -= __bfloat162float(p1);
                    __nv_bfloat16 p2 = __float2bfloat16(rr);
                    int o = (row0m + r) * HH + tid;
                    g_h2s0[o] = p0;  g_h2s1[o] = p1;  g_h2s2[o] = p2;
                }
            }
            grid_bar(G, target);

            // ====== GEMM: G = h2 @ W3 (K=256, bf16 3-split, 6 MMAs, RN FADD accum) ======
            {
                // dX for this tile's 64 rows
                float u2 = 2.f * u, u3 = 3.f * u * u;
                for (int idx = tid; idx < 64 * 20; idx += 256) {
                    int r = idx / 20, d = idx - r * 20;
                    const float* cp = coeffs + ((size_t)(row0g + r) * NSEG + iseg) * 80;
                    dXs[idx] = cp[20 + d] + u2 * cp[40 + d] + u3 * cp[60 + d];
                }
                // A = h2 splits, full K=256 resident (64 rows x 256)
#pragma unroll
                for (int it = 0; it < 8; it++) {
                    int uu = tid + it * 256;          // 0..2047 16B-units
                    int row = uu >> 5, kl8 = uu & 31;
                    size_t so = (size_t)(row0g + row) * 256 + kl8 * 8;
                    uint32_t doff = (uint32_t)(row * APITCH + kl8 * 8) * 2;
                    *(uint4*)(smem + OFF_A0 + doff) = *(const uint4*)&g_h2s0[so];
                    *(uint4*)(smem + OFF_A1 + doff) = *(const uint4*)&g_h2s1[so];
                    *(uint4*)(smem + OFF_A2 + doff) = *(const uint4*)&g_h2s2[so];
                }
                __syncthreads();

#pragma unroll 1
                for (int ns = 0; ns < 16; ns++) {
                    float acc[2][5][4];
                    float tmp[2][5][4];
#pragma unroll
                    for (int mi = 0; mi < 2; mi++)
#pragma unroll
                        for (int np = 0; np < 5; np++)
#pragma unroll
                            for (int q = 0; q < 4; q++) acc[mi][np][q] = 0.f;

#pragma unroll 1
                    for (int kc = 0; kc < 4; kc++) {
                        __syncthreads();   // prev MMA / epilogue done
                        // load B chunk: 160 n-rows x 64 k (3 splits)
#pragma unroll
                        for (int it = 0; it < 5; it++) {
                            int uu = tid + it * 256;       // 0..1279
                            int row = uu >> 3, kl16 = uu & 7;
                            size_t so = (size_t)(col0 + ns * 160 + row) * 256 + kc * 64 + kl16 * 8;
                            uint32_t doff = (uint32_t)(row * BPITCH + kl16 * 8) * 2;
                            *(uint4*)(smem + OFF_B0 + doff) = *(const uint4*)&g_B0[so];
                            *(uint4*)(smem + OFF_B1 + doff) = *(const uint4*)&g_B1[so];
                            *(uint4*)(smem + OFF_B2 + doff) = *(const uint4*)&g_B2[so];
                        }
                        __syncthreads();

                        // 4 k16 per chunk, processed in pairs:
                        //   even k16: tmp = chain of 6 split-MMAs (zero-c init)
                        //   odd  k16: +6 more chained, then ONE RN FADD into acc
#pragma unroll
                        for (int k16 = 0; k16 < 4; k16++) {
                            const int k16g = kc * 4 + k16;
                            const int ev = ((k16 & 1) == 0);
                            uint32_t a0[2][4], a1[2][4], a2[2][4];
#pragma unroll
                            for (int mi = 0; mi < 2; mi++) {
                                uint32_t ao = (uint32_t)(wm * 32 + mi * 16) * (APITCH * 2)
                                            + lma + (uint32_t)k16g * 32;
                                LDSM4(a0[mi], sb + OFF_A0 + ao);
                                LDSM4(a1[mi], sb + OFF_A1 + ao);
                                LDSM4(a2[mi], sb + OFF_A2 + ao);
                            }
#pragma unroll
                            for (int np = 0; np < 5; np++) {
                                uint32_t bo = (uint32_t)(wn * 40 + np * 8) * (BPITCH * 2)
                                            + lmb + (uint32_t)k16 * 32;
                                uint32_t b0[2], b1[2], b2[2];
                                LDSM2(b0, sb + OFF_B0 + bo);
                                LDSM2(b1, sb + OFF_B1 + bo);
                                LDSM2(b2, sb + OFF_B2 + bo);
#pragma unroll
                                for (int mi = 0; mi < 2; mi++) {
                                    if (ev) {
                                        MMA16_INIT(tmp[mi][np], a1[mi], b1[0], b1[1], zc);
                                    } else {
                                        MMA16(tmp[mi][np], a1[mi], b1[0], b1[1]);
                                    }
                                    MMA16(tmp[mi][np], a2[mi], b0[0], b0[1]);
                                    MMA16(tmp[mi][np], a0[mi], b2[0], b2[1]);
                                    MMA16(tmp[mi][np], a1[mi], b0[0], b0[1]);
                                    MMA16(tmp[mi][np], a0[mi], b1[0], b1[1]);
                                    MMA16(tmp[mi][np], a0[mi], b0[0], b0[1]);
                                    if (!ev) {
#pragma unroll
                                        for (int q = 0; q < 4; q++)
                                            acc[mi][np][q] += tmp[mi][np][q];
                                    }
                                }
                            }
                        }
                    }

                    // store G tile to SMEM
                    {
                        const int r0 = wm * 32 + (lane >> 2);
                        const int c0 = wn * 40 + (lane & 3) * 2;
#pragma unroll
                        for (int mi = 0; mi < 2; mi++)
#pragma unroll
                            for (int np = 0; np < 5; np++) {
                                float* p0 = sG + (r0 + mi * 16) * GPITCH + c0 + np * 8;
                                float* p1 = p0 + 8 * GPITCH;
                                p0[0] = acc[mi][np][0];  p0[1] = acc[mi][np][1];
                                p1[0] = acc[mi][np][2];  p1[1] = acc[mi][np][3];
                            }
                    }
                    __syncthreads();

                    // epilogue: 64 rows x 8 h -> g_k (reference-order 20-term d-sum)
#pragma unroll
                    for (int j = 0; j < 2; j++) {
                        int o = tid + j * 256;            // 0..511
                        int row = o >> 3, hl = o & 7;
                        const float* gr = sG + row * GPITCH + hl * 20;
                        const float* br = b3s + ns * 160 + hl * 20;
                        const float* dx = dXs + row * 20;
                        float v = 0.f;
#pragma unroll
                        for (int d = 0; d < 20; d++) v += (gr[d] + br[d]) * dx[d];
                        g_k[s][(size_t)(row0g + row) * 256 + nt * 128 + ns * 8 + hl] = v;
                    }
                }
            }
            grid_bar(G, target);
        }
    }
}

// --------------------------------------------------------------- final head
__device__ __forceinline__ float blockSum(float v, volatile float* s8) {
#pragma unroll
    for (int o = 16; o > 0; o >>= 1) v += __shfl_down_sync(0xffffffffu, v, o);
    if ((threadIdx.x & 31) == 0) s8[threadIdx.x >> 5] = v;
    __syncthreads();
    float t = 0.f;
#pragma unroll
    for (int i = 0; i < 8; i++) t += s8[i];
    __syncthreads();
    return t;
}

__global__ void head_kernel(const float* __restrict__ Ws,  const float* __restrict__ bs,
                            const float* __restrict__ lng, const float* __restrict__ lnb,
                            const float* __restrict__ Winf, const float* __restrict__ binf,
                            const float* __restrict__ Wdet, const float* __restrict__ bdet,
                            const float* __restrict__ Wsur, const float* __restrict__ bsur,
                            float* __restrict__ out) {
    int b = blockIdx.x;
    int c = threadIdx.x;
    __shared__ float zs[256];
    __shared__ float s8[8];

    {
        int idx = b * HH + c;
        float k1 = g_k[0][idx], k2 = g_k[1][idx];
        float k3 = g_k[2][idx], k4 = g_k[3][idx];
        zs[c] = g_z[idx] + (1.f / 12.f) * (k1 + 2.f * k2 + 2.f * k3 + k4);
    }
    __syncthreads();

    float h = 0.f;
#pragma unroll 1
    for (int ch = 0; ch < 8; ch++) {
        float hl = 0.f;
#pragma unroll 4
        for (int ii = 0; ii < 32; ii++) {
            int i = ch * 32 + ii;
            hl += zs[i] * Ws[i * 256 + c];
        }
        h += hl;
    }
    h += bs[c];

    float mu  = blockSum(h, s8) * (1.f / 256.f);
    float dc  = h - mu;
    float var = blockSum(dc * dc, s8) * (1.f / 256.f);
    float r   = lng[c] * dc * rsqrtf(var + 1e-5f) + lnb[c];
    r = fmaxf(r, 0.f);

    out[36864 + (size_t)b * 256 + c] = r;

#pragma unroll
    for (int o = 0; o < 4; o++) {
        float s = blockSum(r * Winf[c * 4 + o], s8);
        if (c == 0) out[(size_t)b * 4 + o] = 1.f / (1.f + expf(-(s + binf[o])));
    }
#pragma unroll
    for (int o = 0; o < 3; o++) {
        float s = blockSum(r * Wdet[c * 3 + o], s8);
        if (c == 0) out[16384 + (size_t)b * 3 + o] = 1.f / (1.f + expf(-(s + bdet[o])));
    }
#pragma unroll
    for (int o = 0; o < 2; o++) {
        float s = blockSum(r * Wsur[c * 2 + o], s8);
        if (c == 0) {
            float x = s + bsur[o];
            out[28672 + (size_t)b * 2 + o] = fmaxf(x, 0.f) + log1pf(expf(-fabsf(x)));
        }
    }
}

// =========================================================== host dispatch
extern "C" void kernel_launch(void* const* d_in, const int* in_sizes, int n_in,
                              void* d_out, int out_size) {
    const float* coeffs = (const float*)d_in[0];
    const float* Wi     = (const float*)d_in[1];
    const float* bi     = (const float*)d_in[2];
    const float* W1     = (const float*)d_in[3];
    const float* b1     = (const float*)d_in[4];
    const float* W2     = (const float*)d_in[5];
    const float* b2     = (const float*)d_in[6];
    const float* W3     = (const float*)d_in[7];
    const float* b3     = (const float*)d_in[8];
    const float* Ws     = (const float*)d_in[9];
    const float* bs     = (const float*)d_in[10];
    const float* lng    = (const float*)d_in[11];
    const float* lnb    = (const float*)d_in[12];
    const float* Winf   = (const float*)d_in[13];
    const float* binf   = (const float*)d_in[14];
    const float* Wdet   = (const float*)d_in[15];
    const float* bdet   = (const float*)d_in[16];
    const float* Wsur   = (const float*)d_in[17];
    const float* bsur   = (const float*)d_in[18];
    float* out = (float*)d_out;

    static int configured = 0;
    if (!configured) {
        cudaFuncSetAttribute(persist, cudaFuncAttributeMaxDynamicSharedMemorySize, SMEM_TOTAL);
        configured = 1;
    }

    reset_barrier<<<1, 1>>>();
    split_w3<<<HD * HH / 256, 256>>>(W3);
    init_z<<<NB, 256>>>(coeffs, Wi, bi);
    persist<<<GRID, 256, SMEM_TOTAL>>>(coeffs, W1, b1, W2, b2, b3, GRID);
    head_kernel<<<NB, 256>>>(Ws, bs, lng, lnb, Winf, binf, Wdet, bdet, Wsur, bsur, out);
}